// round 2
// baseline (speedup 1.0000x reference)
#include <cuda_runtime.h>
#include <math.h>

#define V      50257
#define NT     1024
#define CAP    4096
#define TOPK   100
#define ROWPAD ((V + 3) & ~3)           // 50260, float4-aligned region for the row
#define NITER  ((V + NT - 1) / NT)      // 50 fixed trips so __ballot_sync masks stay full

// 2^y via round-to-int bit trick + degree-5 Taylor on f in [-0.5, 0.5].
// rel err ~3.5e-6, FMA/ALU pipes only (no MUFU). y <= ~0 in our use; clamp
// at -120 so the exponent-add never produces denormal garbage (terms there
// contribute < 1e-36 to a sum >= 1).
__device__ __forceinline__ float exp2_fast(float y) {
    y = fmaxf(y, -120.0f);
    float r = y + 12582912.0f;                 // 1.5*2^23: RN rounds y to int n
    int   n = __float_as_int(r) - 0x4B400000;  // two's-complement n
    float f = y - (r - 12582912.0f);           // exact residual in [-0.5, 0.5]
    float p = 1.3333558146428443e-3f;
    p = fmaf(p, f, 9.6181291076284772e-3f);
    p = fmaf(p, f, 5.5504108664821580e-2f);
    p = fmaf(p, f, 2.4022650695910071e-1f);
    p = fmaf(p, f, 6.9314718055994531e-1f);
    p = fmaf(p, f, 1.0f);                      // p = 2^f in [0.707, 1.415)
    return __uint_as_float(__float_as_uint(p) + ((unsigned)n << 23));
}

extern __shared__ float sm[];

__global__ void __launch_bounds__(NT, 1)
pts_kernel(const float* __restrict__ inp,
           const int* __restrict__ tokens,          // JAX int64 silently downcasts to int32
           const float* __restrict__ W1, const float* __restrict__ b1,
           const float* __restrict__ W2, const float* __restrict__ b2,
           const float* __restrict__ W3, const float* __restrict__ b3,
           float* __restrict__ out)
{
    float* row  = sm;               // [ROWPAD] the full fp32 row
    float* cand = sm + ROWPAD;      // [CAP]    top-candidate values
    float* red  = cand + CAP;       // [32]     block-reduce scratch

    __shared__ float sM, sA, sB;
    __shared__ float sh1[5];
    __shared__ int   sCount;

    const int tid  = threadIdx.x;
    const int lane = tid & 31;
    const int wid  = tid >> 5;
    const int r    = blockIdx.x;
    const float* x = inp + (size_t)r * V;

    // ---------- Phase 1: load row -> smem, fused row max (single HBM read) ----------
    float mx = -INFINITY;
    #pragma unroll 4
    for (int i = tid; i < V; i += NT) {
        float v = __ldg(x + i);
        row[i] = v;
        mx = fmaxf(mx, v);
    }
    #pragma unroll
    for (int o = 16; o; o >>= 1) mx = fmaxf(mx, __shfl_xor_sync(0xffffffffu, mx, o));
    if (lane == 0) red[wid] = mx;
    __syncthreads();
    if (tid < 32) {
        float m = red[tid];
        #pragma unroll
        for (int o = 16; o; o >>= 1) m = fmaxf(m, __shfl_xor_sync(0xffffffffu, m, o));
        if (tid == 0) sM = m;
    }
    __syncthreads();
    const float M = sM;

    // ---------- Phase 2: gather all x > M - delta (bracketing retry; exact superset of top-100) ----------
    float delta = 2.0f, dLo = 0.0f, dHi = 0.0f;
    bool  hasHi = false;
    int   count = 0;
    for (int attempt = 0; attempt < 48; ++attempt) {
        __syncthreads();
        if (tid == 0) sCount = 0;
        __syncthreads();
        const float thr = M - delta;
        for (int it = 0; it < NITER; ++it) {
            int   i = it * NT + tid;
            float v = (i < V) ? row[i] : -INFINITY;
            bool  p = v > thr;
            unsigned msk = __ballot_sync(0xffffffffu, p);
            if (msk) {                               // warp-uniform
                int base = 0;
                if (lane == 0) base = atomicAdd(&sCount, __popc(msk));
                base = __shfl_sync(0xffffffffu, base, 0);
                if (p) {
                    int pos = base + __popc(msk & ((1u << lane) - 1u));
                    if (pos < CAP) cand[pos] = v;
                }
            }
        }
        __syncthreads();
        count = sCount;
        if (count >= TOPK && count <= CAP) break;
        if (count < TOPK) { dLo = delta; delta = hasHi ? 0.5f * (delta + dHi) : delta * 2.0f; }
        else              { dHi = delta; hasHi = true; delta = 0.5f * (delta + dLo); }
    }
    if (count > CAP) count = CAP;

    // ---------- Phase 3: bitonic sort candidates descending ----------
    int P = 128;
    while (P < count) P <<= 1;                      // P <= 4096
    for (int i = count + tid; i < P; i += NT) cand[i] = -INFINITY;
    __syncthreads();
    for (int k = 2; k <= P; k <<= 1) {
        for (int j = k >> 1; j > 0; j >>= 1) {
            for (int i = tid; i < P; i += NT) {
                int ixj = i ^ j;
                if (ixj > i) {
                    float va = cand[i], vb = cand[ixj];
                    bool desc = ((i & k) == 0);
                    if (desc ? (va < vb) : (va > vb)) { cand[i] = vb; cand[ixj] = va; }
                }
            }
            __syncthreads();
        }
    }
    if (count < TOPK) {                             // pathological fallback only
        if (tid == 0) {
            float last = cand[count > 0 ? count - 1 : 0];
            for (int i = count; i < TOPK; ++i) cand[i] = last;
        }
        __syncthreads();
    }

    // ---------- Phase 4: tiny MLP -> temperature -> softmax scale (a, b) ----------
    if (wid < 5) {
        float acc = 0.0f;
        for (int i = lane; i < TOPK; i += 32)
            acc = fmaf(__ldg(W1 + wid * TOPK + i), cand[i], acc);
        #pragma unroll
        for (int o = 16; o; o >>= 1) acc += __shfl_xor_sync(0xffffffffu, acc, o);
        if (lane == 0) sh1[wid] = fmaxf(acc + __ldg(b1 + wid), 0.0f);
    }
    __syncthreads();
    if (tid == 0) {
        float h2[5];
        #pragma unroll
        for (int j = 0; j < 5; ++j) {
            float a2 = __ldg(b2 + j);
            #pragma unroll
            for (int i = 0; i < 5; ++i) a2 = fmaf(__ldg(W2 + j * 5 + i), sh1[i], a2);
            h2[j] = fmaxf(a2, 0.0f);
        }
        float t0 = __ldg(b3);
        #pragma unroll
        for (int i = 0; i < 5; ++i) t0 = fmaf(__ldg(W3 + i), h2[i], t0);
        t0 = fabsf(t0);
        float sp   = (t0 > 20.0f) ? t0 : log1pf(expf(t0));   // stable softplus
        float temp = fmaxf(sp, 1e-5f);
        float a    = 1.44269504088896340736f / temp;          // log2(e)/temp
        sA = a;
        sB = -M * a;                                          // 2^(x*a + b) = exp((x-M)/temp)
    }
    __syncthreads();
    const float a = sA, b = sB;

    // ---------- Phase 5: softmax denominator over smem row (FMA-only exp2) ----------
    float s0 = 0.0f, s1 = 0.0f;
    const float4* row4 = (const float4*)row;
    const int NQ = V >> 2;                          // 12564 quads
    for (int i = tid; i < NQ; i += NT) {
        float4 v = row4[i];
        s0 += exp2_fast(fmaf(v.x, a, b));
        s1 += exp2_fast(fmaf(v.y, a, b));
        s0 += exp2_fast(fmaf(v.z, a, b));
        s1 += exp2_fast(fmaf(v.w, a, b));
    }
    for (int i = (NQ << 2) + tid; i < V; i += NT)   // tail (1 element)
        s0 += exp2_fast(fmaf(row[i], a, b));
    float sum = s0 + s1;
    #pragma unroll
    for (int o = 16; o; o >>= 1) sum += __shfl_xor_sync(0xffffffffu, sum, o);
    if (lane == 0) red[wid] = sum;
    __syncthreads();

    // ---------- Phase 6: gather token probability ----------
    if (tid == 0) {
        float tot = 0.0f;
        #pragma unroll
        for (int i = 0; i < 32; ++i) tot += red[i];
        int tok = tokens[r];
        tok = (tok < 0) ? 0 : ((tok >= V) ? V - 1 : tok);   // fail-soft, never OOB
        float xt = row[tok];
        out[r] = exp2_fast(fmaf(xt, a, b)) / tot;
    }
}

extern "C" void kernel_launch(void* const* d_in, const int* in_sizes, int n_in,
                              void* d_out, int out_size)
{
    const float* inp    = (const float*)d_in[0];
    const int*   tokens = (const int*)d_in[1];
    const float* W1     = (const float*)d_in[2];
    const float* b1     = (const float*)d_in[3];
    const float* W2     = (const float*)d_in[4];
    const float* b2     = (const float*)d_in[5];
    const float* W3     = (const float*)d_in[6];
    const float* b3     = (const float*)d_in[7];
    float*       o      = (float*)d_out;

    const int N = in_sizes[1];  // number of rows = token count (4096)

    size_t smem = (size_t)(ROWPAD + CAP + 32) * sizeof(float);  // ~212.5 KB
    cudaFuncSetAttribute(pts_kernel, cudaFuncAttributeMaxDynamicSharedMemorySize, (int)smem);

    pts_kernel<<<N, NT, smem>>>(inp, tokens, W1, b1, W2, b2, W3, b3, o);
}

// round 3
// speedup vs baseline: 1.6261x; 1.6261x over previous
#include <cuda_runtime.h>
#include <math.h>

#define VV      50257
#define NT1     256
#define NW      8             // warps per K1 block
#define WCAP    2048          // per-warp candidate capacity
#define CAP     (NW*WCAP)     // 16384
#define FCAP    256           // finalist buffer (== NT1)
#define TOPK    100
#define DELTA0  2.2f
#define SEG     4
#define SEGLEN  12565
#define MAXN    8192
#define NT2     256
#define KFULL   24            // full 8x256 batches: covers [0, 49152)
#define TAILI   5             // tail iterations covering [49152, 50257)

__device__ float g_a[MAXN];
__device__ float g_b[MAXN];
__device__ float g_part[MAXN * SEG];

// 2^y via round-to-int bit trick + degree-5 poly on [-0.5,0.5]; FMA/ALU only.
__device__ __forceinline__ float exp2_fast(float y) {
    y = fmaxf(y, -120.0f);
    float r = y + 12582912.0f;
    int   n = __float_as_int(r) - 0x4B400000;
    float f = y - (r - 12582912.0f);
    float p = 1.3333558146428443e-3f;
    p = fmaf(p, f, 9.6181291076284772e-3f);
    p = fmaf(p, f, 5.5504108664821580e-2f);
    p = fmaf(p, f, 2.4022650695910071e-1f);
    p = fmaf(p, f, 6.9314718055994531e-1f);
    p = fmaf(p, f, 1.0f);
    return __uint_as_float(__float_as_uint(p) + ((unsigned)n << 23));
}

// ---------------- block reduction helpers (K1: 8 warps) ----------------
__device__ __forceinline__ float blockMaxF(float v, float* red, int tid) {
    int lane = tid & 31, w = tid >> 5;
    #pragma unroll
    for (int k = 16; k; k >>= 1) v = fmaxf(v, __shfl_xor_sync(~0u, v, k));
    if (lane == 0) red[w] = v;
    __syncthreads();
    if (tid < 32) {
        float m = (tid < NW) ? red[tid] : -INFINITY;
        #pragma unroll
        for (int k = 4; k; k >>= 1) m = fmaxf(m, __shfl_xor_sync(~0u, m, k));
        if (tid == 0) red[0] = m;
    }
    __syncthreads();
    float r = red[0];
    __syncthreads();
    return r;
}
__device__ __forceinline__ float blockMinF(float v, float* red, int tid) {
    int lane = tid & 31, w = tid >> 5;
    #pragma unroll
    for (int k = 16; k; k >>= 1) v = fminf(v, __shfl_xor_sync(~0u, v, k));
    if (lane == 0) red[w] = v;
    __syncthreads();
    if (tid < 32) {
        float m = (tid < NW) ? red[tid] : INFINITY;
        #pragma unroll
        for (int k = 4; k; k >>= 1) m = fminf(m, __shfl_xor_sync(~0u, m, k));
        if (tid == 0) red[0] = m;
    }
    __syncthreads();
    float r = red[0];
    __syncthreads();
    return r;
}
__device__ __forceinline__ int blockSumI(int v, int* redi, int tid) {
    int lane = tid & 31, w = tid >> 5;
    #pragma unroll
    for (int k = 16; k; k >>= 1) v += __shfl_xor_sync(~0u, v, k);
    if (lane == 0) redi[w] = v;
    __syncthreads();
    if (tid < 32) {
        int s = (tid < NW) ? redi[tid] : 0;
        #pragma unroll
        for (int k = 4; k; k >>= 1) s += __shfl_xor_sync(~0u, s, k);
        if (tid == 0) redi[0] = s;
    }
    __syncthreads();
    int r = redi[0];
    __syncthreads();
    return r;
}

// Stream the row from global, gather values > thr into per-warp smem regions
// using register counters (no atomics). Also returns per-thread max/min.
__device__ __forceinline__ void gatherStream(
    const float* __restrict__ x, float thr,
    float* cand, int* wcnts, int tid, float* pmx, float* pmn)
{
    const int lane = tid & 31, w = tid >> 5;
    const unsigned lmask = (1u << lane) - 1u;
    int wcnt = 0;
    float mx = -INFINITY, mn = INFINITY;
    #pragma unroll 1
    for (int k = 0; k < KFULL; k++) {
        int base = tid + k * (8 * NT1);
        float v[8];
        #pragma unroll
        for (int j = 0; j < 8; j++) v[j] = __ldg(x + base + j * NT1);
        #pragma unroll
        for (int j = 0; j < 8; j++) {
            float vv = v[j];
            mx = fmaxf(mx, vv);
            mn = fminf(mn, vv);
            unsigned m = __ballot_sync(~0u, vv > thr);
            if (m) {
                int pos = wcnt + __popc(m & lmask);
                if (vv > thr && pos < WCAP) cand[w * WCAP + pos] = vv;
                wcnt += __popc(m);
            }
        }
    }
    #pragma unroll
    for (int t = 0; t < TAILI; t++) {
        int i = KFULL * (8 * NT1) + t * NT1 + tid;
        bool in = (i < VV);
        float vv = in ? __ldg(x + i) : -INFINITY;
        if (in) { mx = fmaxf(mx, vv); mn = fminf(mn, vv); }
        unsigned m = __ballot_sync(~0u, in && (vv > thr));
        if (m) {
            int pos = wcnt + __popc(m & lmask);
            if (in && vv > thr && pos < WCAP) cand[w * WCAP + pos] = vv;
            wcnt += __popc(m);
        }
    }
    if (lane == 0) wcnts[w] = wcnt;
    *pmx = mx;
    *pmn = mn;
}

// count of candidates (> t) over segmented smem buffer
__device__ __forceinline__ int cgtSmem(const float* cand, const int* wcnts, float t,
                                       int tid, int* redi) {
    int c = 0;
    #pragma unroll 4
    for (int s = tid; s < CAP; s += NT1) {
        int w = s / WCAP, i = s % WCAP;
        c += (i < wcnts[w] && cand[s] > t);
    }
    return blockSumI(c, redi, tid);
}

// count of row elements (> t) read from global (fallback path)
__device__ __forceinline__ int cgtGlobal(const float* __restrict__ x, float t,
                                         int tid, int* redi) {
    int c = 0;
    #pragma unroll 8
    for (int i = tid; i < VV; i += NT1) c += (__ldg(x + i) > t);
    return blockSumI(c, redi, tid);
}

extern __shared__ float smk1[];

__global__ void __launch_bounds__(NT1)
k1_topk(const float* __restrict__ inp,
        const float* __restrict__ W1, const float* __restrict__ b1,
        const float* __restrict__ W2, const float* __restrict__ b2,
        const float* __restrict__ W3, const float* __restrict__ b3)
{
    float* cand = smk1;           // [CAP]
    float* buf  = smk1 + CAP;     // [FCAP]
    __shared__ int   wcnts[NW];
    __shared__ float redf[NW];
    __shared__ int   redi[NW];
    __shared__ int   sCnt;
    __shared__ float sh1[5];

    const int tid  = threadIdx.x;
    const int lane = tid & 31;
    const int wid  = tid >> 5;
    const int row  = blockIdx.x;
    const float* x = inp + (size_t)row * VV;

    // ---- sample 4096 elems (16 coalesced 1KB bursts) for threshold init ----
    float sx = -INFINITY;
    #pragma unroll
    for (int j = 0; j < 16; j++) sx = fmaxf(sx, __ldg(x + j * 3141 + tid));
    float sampmax = blockMaxF(sx, redf, tid);
    float thr = sampmax - DELTA0;

    // ---- single streaming pass: gather + exact max/min ----
    float mx, mn;
    gatherStream(x, thr, cand, wcnts, tid, &mx, &mn);
    __syncthreads();
    float M  = blockMaxF(mx, redf, tid);
    float MN = blockMinF(mn, redf, tid);

    // ---- totals + overflow detect ----
    if (tid < 32) {
        int c = (tid < NW) ? wcnts[tid] : 0;
        int o = (c > WCAP) ? 1 : 0;
        int cc = (c > WCAP) ? WCAP : c;
        #pragma unroll
        for (int k = 16; k; k >>= 1) { cc += __shfl_xor_sync(~0u, cc, k); o += __shfl_xor_sync(~0u, o, k); }
        if (tid == 0) { redi[0] = cc; redi[1] = o; }
    }
    __syncthreads();
    int C = redi[0];
    int bad = (redi[1] != 0) || (C < TOPK);
    if (tid < NW) wcnts[tid] = min(wcnts[tid], WCAP);
    __syncthreads();

    float thrEff = thr;
    if (bad) {
        // ---- rare fallback: bisect a workable threshold on global data ----
        float lo = MN - 1.0f, hi = M;
        float t = hi; int found = 0;
        for (int it = 0; it < 40 && !found; it++) {
            float mid = 0.5f * (lo + hi);
            if (mid <= lo || mid >= hi) break;          // ulp-adjacent: plateau
            int c = cgtGlobal(x, mid, tid, redi);
            if (c >= TOPK && c <= CAP - 2048) { t = mid; found = 1; }
            else if (c > CAP - 2048) lo = mid; else hi = mid;
        }
        if (!found) t = hi;
        thrEff = t;
        gatherStream(x, thrEff, cand, wcnts, tid, &mx, &mn);
        __syncthreads();
        if (tid < 32) {
            int c = (tid < NW) ? min(wcnts[tid], WCAP) : 0;
            #pragma unroll
            for (int k = 16; k; k >>= 1) c += __shfl_xor_sync(~0u, c, k);
            if (tid == 0) redi[0] = c;
        }
        __syncthreads();
        C = redi[0];
        if (tid < NW) wcnts[tid] = min(wcnts[tid], WCAP);
        __syncthreads();
    }

    // ---- bisect on the candidate set to land count in [TOPK, FCAP] ----
    float tSel = thrEff;
    if (C > FCAP) {
        float lo = thrEff, hi = M;
        int found = 0;
        for (int it = 0; it < 40 && !found; it++) {
            float mid = 0.5f * (lo + hi);
            if (mid <= lo || mid >= hi) break;          // tie plateau -> use hi
            int c = cgtSmem(cand, wcnts, mid, tid, redi);
            if (c >= TOPK && c <= FCAP) { tSel = mid; found = 1; }
            else if (c > FCAP) lo = mid; else hi = mid;
        }
        if (!found) tSel = hi;
    }

    // ---- gather finalists (> tSel) into buf ----
    if (tid == 0) sCnt = 0;
    __syncthreads();
    {
        const unsigned lmask = (1u << lane) - 1u;
        #pragma unroll 4
        for (int s = tid; s < CAP; s += NT1) {
            int w = s / WCAP, i = s % WCAP;
            float v = (i < wcnts[w]) ? cand[s] : -INFINITY;
            bool p = v > tSel;
            unsigned m = __ballot_sync(~0u, p);
            if (m) {
                int base;
                if (lane == 0) base = atomicAdd(&sCnt, __popc(m));
                base = __shfl_sync(~0u, base, 0);
                if (p) {
                    int pos = base + __popc(m & lmask);
                    if (pos < FCAP) buf[pos] = v;
                }
            }
        }
    }
    __syncthreads();
    int bc = min(sCnt, FCAP);
    if (tid >= bc) buf[tid] = -INFINITY;                // pad (NT1 == FCAP)
    __syncthreads();

    // ---- bitonic sort 256 descending ----
    #pragma unroll 1
    for (int k = 2; k <= FCAP; k <<= 1) {
        #pragma unroll 1
        for (int j = k >> 1; j > 0; j >>= 1) {
            int i = tid, ixj = i ^ j;
            if (ixj > i) {
                float va = buf[i], vb = buf[ixj];
                bool desc = ((i & k) == 0);
                if (desc ? (va < vb) : (va > vb)) { buf[i] = vb; buf[ixj] = va; }
            }
            __syncthreads();
        }
    }
    // tie-plateau fill: if fewer than TOPK strictly-greater elems, the rest equal tSel
    if (tid < TOPK && tid >= bc) buf[tid] = tSel;
    __syncthreads();

    // ---- tiny MLP -> temperature -> (a, b) ----
    if (wid < 5) {
        float acc = 0.0f;
        #pragma unroll
        for (int i = lane; i < TOPK; i += 32)
            acc = fmaf(__ldg(W1 + wid * TOPK + i), buf[i], acc);
        #pragma unroll
        for (int k = 16; k; k >>= 1) acc += __shfl_xor_sync(~0u, acc, k);
        if (lane == 0) sh1[wid] = fmaxf(acc + __ldg(b1 + wid), 0.0f);
    }
    __syncthreads();
    if (tid == 0) {
        float h2[5];
        #pragma unroll
        for (int j = 0; j < 5; ++j) {
            float a2 = __ldg(b2 + j);
            #pragma unroll
            for (int i = 0; i < 5; ++i) a2 = fmaf(__ldg(W2 + j * 5 + i), sh1[i], a2);
            h2[j] = fmaxf(a2, 0.0f);
        }
        float t0 = __ldg(b3);
        #pragma unroll
        for (int i = 0; i < 5; ++i) t0 = fmaf(__ldg(W3 + i), h2[i], t0);
        t0 = fabsf(t0);
        float sp   = (t0 > 20.0f) ? t0 : log1pf(expf(t0));
        float temp = fmaxf(sp, 1e-5f);
        float a    = 1.44269504088896340736f / temp;
        g_a[row] = a;
        g_b[row] = -M * a;
    }
}

__global__ void __launch_bounds__(NT2)
k2_sumexp(const float* __restrict__ inp)
{
    const int row = blockIdx.x >> 2;
    const int seg = blockIdx.x & 3;
    const int tid = threadIdx.x;
    const float* x = inp + (size_t)row * VV;
    const float a = __ldg(&g_a[row]);
    const float b = __ldg(&g_b[row]);
    const int start = seg * SEGLEN;
    const int end   = min(VV, start + SEGLEN);

    float s = 0.0f;
    int i = start + tid;
    for (; i + 7 * NT2 < end; i += 8 * NT2) {
        float v[8];
        #pragma unroll
        for (int j = 0; j < 8; j++) v[j] = __ldg(x + i + j * NT2);
        #pragma unroll
        for (int j = 0; j < 8; j++) s += exp2_fast(fmaf(v[j], a, b));
    }
    for (; i < end; i += NT2) s += exp2_fast(fmaf(__ldg(x + i), a, b));

    __shared__ float red[8];
    int lane = tid & 31, w = tid >> 5;
    #pragma unroll
    for (int k = 16; k; k >>= 1) s += __shfl_xor_sync(~0u, s, k);
    if (lane == 0) red[w] = s;
    __syncthreads();
    if (tid == 0) {
        float tot = 0.0f;
        #pragma unroll
        for (int k = 0; k < NT2 / 32; k++) tot += red[k];
        g_part[row * SEG + seg] = tot;
    }
}

__global__ void k3_final(const float* __restrict__ inp,
                         const int* __restrict__ tokens,
                         float* __restrict__ out, int nrows)
{
    int r = blockIdx.x * blockDim.x + threadIdx.x;
    if (r >= nrows) return;
    float s = g_part[r * SEG + 0] + g_part[r * SEG + 1]
            + g_part[r * SEG + 2] + g_part[r * SEG + 3];
    int tok = tokens[r];
    tok = (tok < 0) ? 0 : ((tok >= VV) ? VV - 1 : tok);
    float xt = __ldg(inp + (size_t)r * VV + tok);
    out[r] = exp2_fast(fmaf(xt, g_a[r], g_b[r])) / s;
}

extern "C" void kernel_launch(void* const* d_in, const int* in_sizes, int n_in,
                              void* d_out, int out_size)
{
    const float* inp    = (const float*)d_in[0];
    const int*   tokens = (const int*)d_in[1];
    const float* W1     = (const float*)d_in[2];
    const float* b1     = (const float*)d_in[3];
    const float* W2     = (const float*)d_in[4];
    const float* b2     = (const float*)d_in[5];
    const float* W3     = (const float*)d_in[6];
    const float* b3     = (const float*)d_in[7];
    float*       o      = (float*)d_out;

    int N = in_sizes[1];
    if (N > MAXN) N = MAXN;

    size_t sm1 = (size_t)(CAP + FCAP) * sizeof(float);   // ~66.5 KB
    cudaFuncSetAttribute(k1_topk, cudaFuncAttributeMaxDynamicSharedMemorySize, (int)sm1);

    k1_topk<<<N, NT1, sm1>>>(inp, W1, b1, W2, b2, W3, b3);
    k2_sumexp<<<N * SEG, NT2>>>(inp);
    k3_final<<<(N + 255) / 256, 256>>>(inp, tokens, o, N);
}

// round 4
// speedup vs baseline: 2.5646x; 1.5771x over previous
#include <cuda_runtime.h>
#include <math.h>

#define VV      50257
#define NT1     256
#define PCAP    32                   // per-thread candidate slots
#define CAP     (PCAP*NT1)           // 8192
#define FCAP    256                  // finalist buffer (== NT1)
#define TOPK    100
#define NSAMP   4096                 // sample size (16 per thread)
#define SEG     4
#define SEGLEN  12565
#define MAXN    8192
#define NT2     256
#define KF      24                   // 24 batches of 8x256 -> [0, 49152)
#define TAILI   5

__device__ float g_a[MAXN];
__device__ float g_b[MAXN];
__device__ float g_part[MAXN * SEG];

// 2^y via round-to-int bit trick + degree-5 poly; FMA/ALU only, no MUFU.
__device__ __forceinline__ float exp2_fast(float y) {
    y = fmaxf(y, -120.0f);
    float r = y + 12582912.0f;
    int   n = __float_as_int(r) - 0x4B400000;
    float f = y - (r - 12582912.0f);
    float p = 1.3333558146428443e-3f;
    p = fmaf(p, f, 9.6181291076284772e-3f);
    p = fmaf(p, f, 5.5504108664821580e-2f);
    p = fmaf(p, f, 2.4022650695910071e-1f);
    p = fmaf(p, f, 6.9314718055994531e-1f);
    p = fmaf(p, f, 1.0f);
    return __uint_as_float(__float_as_uint(p) + ((unsigned)n << 23));
}

// ---------------- block reductions (8 warps) ----------------
__device__ __forceinline__ float blockMaxF(float v, float* red, int tid) {
    int lane = tid & 31, w = tid >> 5;
    #pragma unroll
    for (int k = 16; k; k >>= 1) v = fmaxf(v, __shfl_xor_sync(~0u, v, k));
    if (lane == 0) red[w] = v;
    __syncthreads();
    if (tid < 32) {
        float m = (tid < 8) ? red[tid] : -INFINITY;
        #pragma unroll
        for (int k = 4; k; k >>= 1) m = fmaxf(m, __shfl_xor_sync(~0u, m, k));
        if (tid == 0) red[0] = m;
    }
    __syncthreads();
    float r = red[0]; __syncthreads();
    return r;
}
__device__ __forceinline__ float blockMinF(float v, float* red, int tid) {
    int lane = tid & 31, w = tid >> 5;
    #pragma unroll
    for (int k = 16; k; k >>= 1) v = fminf(v, __shfl_xor_sync(~0u, v, k));
    if (lane == 0) red[w] = v;
    __syncthreads();
    if (tid < 32) {
        float m = (tid < 8) ? red[tid] : INFINITY;
        #pragma unroll
        for (int k = 4; k; k >>= 1) m = fminf(m, __shfl_xor_sync(~0u, m, k));
        if (tid == 0) red[0] = m;
    }
    __syncthreads();
    float r = red[0]; __syncthreads();
    return r;
}
__device__ __forceinline__ int blockSumI(int v, int* redi, int tid) {
    int lane = tid & 31, w = tid >> 5;
    #pragma unroll
    for (int k = 16; k; k >>= 1) v += __shfl_xor_sync(~0u, v, k);
    if (lane == 0) redi[w] = v;
    __syncthreads();
    if (tid < 32) {
        int s = (tid < 8) ? redi[tid] : 0;
        #pragma unroll
        for (int k = 4; k; k >>= 1) s += __shfl_xor_sync(~0u, s, k);
        if (tid == 0) redi[0] = s;
    }
    __syncthreads();
    int r = redi[0]; __syncthreads();
    return r;
}
__device__ __forceinline__ int blockMaxI(int v, int* redi, int tid) {
    int lane = tid & 31, w = tid >> 5;
    #pragma unroll
    for (int k = 16; k; k >>= 1) v = max(v, __shfl_xor_sync(~0u, v, k));
    if (lane == 0) redi[w] = v;
    __syncthreads();
    if (tid < 32) {
        int s = (tid < 8) ? redi[tid] : 0;
        #pragma unroll
        for (int k = 4; k; k >>= 1) s = max(s, __shfl_xor_sync(~0u, s, k));
        if (tid == 0) redi[0] = s;
    }
    __syncthreads();
    int r = redi[0]; __syncthreads();
    return r;
}

// count of row elements (> t), full global scan (fallback only)
__device__ __forceinline__ int cgtGlobal(const float* __restrict__ x, float t,
                                         int tid, int* redi) {
    int c = 0;
    #pragma unroll 8
    for (int i = tid; i < VV; i += NT1) c += (__ldg(x + i) > t);
    return blockSumI(c, redi, tid);
}

extern __shared__ float smk1[];

__global__ void __launch_bounds__(NT1, 6)
k1_topk(const float* __restrict__ inp,
        const float* __restrict__ W1, const float* __restrict__ b1,
        const float* __restrict__ W2, const float* __restrict__ b2,
        const float* __restrict__ W3, const float* __restrict__ b3)
{
    float* cand = smk1;           // [CAP]  per-thread columns: cand[c*NT1 + tid]
    float* samp = smk1;           // [NSAMP] overlays cand (dead after threshold pick)
    float* buf  = smk1 + CAP;     // [FCAP]
    __shared__ float redf[8];
    __shared__ int   redi[8];
    __shared__ int   sCnt;
    __shared__ float sh1[5];

    const int tid  = threadIdx.x;
    const int lane = tid & 31;
    const int wid  = tid >> 5;
    const int row  = blockIdx.x;
    const float* x = inp + (size_t)row * VV;

    // ---- Phase A: 4096-elem strided sample into smem + sampled max ----
    float sx = -INFINITY;
    #pragma unroll
    for (int j = 0; j < 16; j++) {
        float s = __ldg(x + j * 3141 + tid);
        samp[j * NT1 + tid] = s;
        sx = fmaxf(sx, s);
    }
    float sampmax = blockMaxF(sx, redf, tid);

    // ---- Phase B: bisect threshold on the sample; target count in [32, 96] ----
    float t;
    {
        float gap = 8.0f, lo = sampmax - gap, hi = sampmax;
        // count of samples > v
        auto countSamp = [&](float v) {
            int c = 0;
            #pragma unroll
            for (int j = 0; j < 16; j++) c += (samp[j * NT1 + tid] > v);
            return blockSumI(c, redi, tid);
        };
        int clo = countSamp(lo);
        for (int wdn = 0; wdn < 25 && clo < 32; wdn++) {
            gap *= 4.0f; lo = sampmax - gap;
            clo = countSamp(lo);
        }
        t = lo;
        if (clo > 96) {
            int found = 0;
            for (int it = 0; it < 30 && !found; it++) {
                float mid = 0.5f * (lo + hi);
                if (mid <= lo || mid >= hi) { t = hi; break; }   // tie plateau
                int c = countSamp(mid);
                if (c >= 32 && c <= 96) { t = mid; found = 1; }
                else if (c > 96) lo = mid; else hi = mid;
            }
            if (!found && t != hi) t = hi;                        // exhausted: prefer fewer
        }
    }

    // ---- Phase C: single streaming pass: exact max/min + per-thread gather ----
    float mx = -INFINITY, mn = INFINITY;
    int   cnt = 0;
    #pragma unroll 1
    for (int k = 0; k < KF; k++) {
        int base = k * (8 * NT1) + tid;
        float v[8];
        #pragma unroll
        for (int j = 0; j < 8; j++) v[j] = __ldg(x + base + j * NT1);
        #pragma unroll
        for (int j = 0; j < 8; j++) {
            float vv = v[j];
            mx = fmaxf(mx, vv);
            mn = fminf(mn, vv);
            if (vv > t) {
                if (cnt < PCAP) cand[cnt * NT1 + tid] = vv;
                cnt++;
            }
        }
    }
    #pragma unroll
    for (int tt = 0; tt < TAILI; tt++) {
        int i = KF * (8 * NT1) + tt * NT1 + tid;
        if (i < VV) {
            float vv = __ldg(x + i);
            mx = fmaxf(mx, vv);
            mn = fminf(mn, vv);
            if (vv > t) {
                if (cnt < PCAP) cand[cnt * NT1 + tid] = vv;
                cnt++;
            }
        }
    }
    __syncthreads();                      // cand fully written (overlays samp)
    float M  = blockMaxF(mx, redf, tid);
    float MN = blockMinF(mn, redf, tid);
    int   C    = blockSumI(cnt, redi, tid);
    int   cmax = blockMaxI(cnt, redi, tid);
    int   bad  = (cmax > PCAP) || (C < TOPK);

    float tSel;
    if (bad) {
        // ---- rare exact fallback: global bisection, gather straight into buf ----
        float lo = MN - 1.0f, hi = M;
        float ts = hi; int found = 0;
        for (int it = 0; it < 60 && !found; it++) {
            float mid = 0.5f * (lo + hi);
            if (mid <= lo || mid >= hi) break;
            int c = cgtGlobal(x, mid, tid, redi);
            if (c >= TOPK && c <= FCAP) { ts = mid; found = 1; }
            else if (c > FCAP) lo = mid; else hi = mid;
        }
        if (!found) ts = hi;
        tSel = ts;
        if (tid == 0) sCnt = 0;
        __syncthreads();
        #pragma unroll 4
        for (int i = tid; i < VV; i += NT1) {
            float vv = __ldg(x + i);
            if (vv > tSel) {
                int pos = atomicAdd(&sCnt, 1);
                if (pos < FCAP) buf[pos] = vv;
            }
        }
        __syncthreads();
    } else {
        // ---- Phase D: bisect on candidate set if count > FCAP ----
        tSel = t;
        if (C > FCAP) {
            float lo = t, hi = M;
            int found = 0;
            for (int it = 0; it < 40 && !found; it++) {
                float mid = 0.5f * (lo + hi);
                if (mid <= lo || mid >= hi) { tSel = hi; break; }
                int c = 0;
                for (int j = 0; j < cnt; j++) c += (cand[j * NT1 + tid] > mid);
                c = blockSumI(c, redi, tid);
                if (c >= TOPK && c <= FCAP) { tSel = mid; found = 1; }
                else if (c > FCAP) lo = mid; else hi = mid;
            }
            if (!found && tSel == t) tSel = hi;
        }
        // ---- Phase E: gather finalists from own slots ----
        if (tid == 0) sCnt = 0;
        __syncthreads();
        for (int j = 0; j < cnt; j++) {
            float vv = cand[j * NT1 + tid];
            if (vv > tSel) {
                int pos = atomicAdd(&sCnt, 1);
                if (pos < FCAP) buf[pos] = vv;
            }
        }
        __syncthreads();
    }

    int bc = min(sCnt, FCAP);
    if (tid >= bc) buf[tid] = -INFINITY;   // pad (NT1 == FCAP)
    __syncthreads();

    // ---- Phase F: bitonic sort 256 descending ----
    #pragma unroll 1
    for (int k = 2; k <= FCAP; k <<= 1) {
        #pragma unroll 1
        for (int j = k >> 1; j > 0; j >>= 1) {
            int i = tid, ixj = i ^ j;
            if (ixj > i) {
                float va = buf[i], vb = buf[ixj];
                bool desc = ((i & k) == 0);
                if (desc ? (va < vb) : (va > vb)) { buf[i] = vb; buf[ixj] = va; }
            }
            __syncthreads();
        }
    }
    // tie-plateau fill: missing entries equal tSel by construction
    if (tid < TOPK && tid >= bc) buf[tid] = tSel;
    __syncthreads();

    // ---- Phase G: tiny MLP -> temperature -> (a, b) ----
    if (wid < 5) {
        float acc = 0.0f;
        #pragma unroll
        for (int i = lane; i < TOPK; i += 32)
            acc = fmaf(__ldg(W1 + wid * TOPK + i), buf[i], acc);
        #pragma unroll
        for (int k = 16; k; k >>= 1) acc += __shfl_xor_sync(~0u, acc, k);
        if (lane == 0) sh1[wid] = fmaxf(acc + __ldg(b1 + wid), 0.0f);
    }
    __syncthreads();
    if (tid == 0) {
        float h2[5];
        #pragma unroll
        for (int j = 0; j < 5; ++j) {
            float a2 = __ldg(b2 + j);
            #pragma unroll
            for (int i = 0; i < 5; ++i) a2 = fmaf(__ldg(W2 + j * 5 + i), sh1[i], a2);
            h2[j] = fmaxf(a2, 0.0f);
        }
        float t0 = __ldg(b3);
        #pragma unroll
        for (int i = 0; i < 5; ++i) t0 = fmaf(__ldg(W3 + i), h2[i], t0);
        t0 = fabsf(t0);
        float sp   = (t0 > 20.0f) ? t0 : log1pf(expf(t0));
        float temp = fmaxf(sp, 1e-5f);
        float a    = 1.44269504088896340736f / temp;
        g_a[row] = a;
        g_b[row] = -M * a;
    }
}

__global__ void __launch_bounds__(NT2)
k2_sumexp(const float* __restrict__ inp)
{
    const int row = blockIdx.x >> 2;
    const int seg = blockIdx.x & 3;
    const int tid = threadIdx.x;
    const float* x = inp + (size_t)row * VV;
    const float a = __ldg(&g_a[row]);
    const float b = __ldg(&g_b[row]);
    const int start = seg * SEGLEN;
    const int end   = min(VV, start + SEGLEN);

    float s = 0.0f;
    int i = start + tid;
    for (; i + 7 * NT2 < end; i += 8 * NT2) {
        float v[8];
        #pragma unroll
        for (int j = 0; j < 8; j++) v[j] = __ldg(x + i + j * NT2);
        #pragma unroll
        for (int j = 0; j < 8; j++) s += exp2_fast(fmaf(v[j], a, b));
    }
    for (; i < end; i += NT2) s += exp2_fast(fmaf(__ldg(x + i), a, b));

    __shared__ float red[8];
    int lane = tid & 31, w = tid >> 5;
    #pragma unroll
    for (int k = 16; k; k >>= 1) s += __shfl_xor_sync(~0u, s, k);
    if (lane == 0) red[w] = s;
    __syncthreads();
    if (tid == 0) {
        float tot = 0.0f;
        #pragma unroll
        for (int k = 0; k < NT2 / 32; k++) tot += red[k];
        g_part[row * SEG + seg] = tot;
    }
}

__global__ void k3_final(const float* __restrict__ inp,
                         const int* __restrict__ tokens,
                         float* __restrict__ out, int nrows)
{
    int r = blockIdx.x * blockDim.x + threadIdx.x;
    if (r >= nrows) return;
    float s = g_part[r * SEG + 0] + g_part[r * SEG + 1]
            + g_part[r * SEG + 2] + g_part[r * SEG + 3];
    int tok = tokens[r];
    tok = (tok < 0) ? 0 : ((tok >= VV) ? VV - 1 : tok);
    float xt = __ldg(inp + (size_t)r * VV + tok);
    out[r] = exp2_fast(fmaf(xt, g_a[r], g_b[r])) / s;
}

extern "C" void kernel_launch(void* const* d_in, const int* in_sizes, int n_in,
                              void* d_out, int out_size)
{
    const float* inp    = (const float*)d_in[0];
    const int*   tokens = (const int*)d_in[1];
    const float* W1     = (const float*)d_in[2];
    const float* b1     = (const float*)d_in[3];
    const float* W2     = (const float*)d_in[4];
    const float* b2     = (const float*)d_in[5];
    const float* W3     = (const float*)d_in[6];
    const float* b3     = (const float*)d_in[7];
    float*       o      = (float*)d_out;

    int N = in_sizes[1];
    if (N > MAXN) N = MAXN;

    size_t sm1 = (size_t)(CAP + FCAP) * sizeof(float);   // 33 KB
    cudaFuncSetAttribute(k1_topk, cudaFuncAttributeMaxDynamicSharedMemorySize, (int)sm1);

    k1_topk<<<N, NT1, sm1>>>(inp, W1, b1, W2, b2, W3, b3);
    k2_sumexp<<<N * SEG, NT2>>>(inp);
    k3_final<<<(N + 255) / 256, 256>>>(inp, tokens, o, N);
}

// round 5
// speedup vs baseline: 2.6173x; 1.0206x over previous
#include <cuda_runtime.h>
#include <math.h>

#define VV      50257
#define NT1     256
#define FCAP    512                  // finalist buffer
#define TOPK    100
#define CS_LO   16                   // sample-count target window
#define CS_HI   32
#define SEG     4
#define SEGLEN  12565
#define MAXN    8192
#define NT2     256

__device__ float g_a[MAXN];
__device__ float g_b[MAXN];
__device__ float g_part[MAXN * SEG];

// 2^y via round-to-int bit trick + degree-5 poly; FMA/ALU only, no MUFU.
__device__ __forceinline__ float exp2_fast(float y) {
    y = fmaxf(y, -120.0f);
    float r = y + 12582912.0f;
    int   n = __float_as_int(r) - 0x4B400000;
    float f = y - (r - 12582912.0f);
    float p = 1.3333558146428443e-3f;
    p = fmaf(p, f, 9.6181291076284772e-3f);
    p = fmaf(p, f, 5.5504108664821580e-2f);
    p = fmaf(p, f, 2.4022650695910071e-1f);
    p = fmaf(p, f, 6.9314718055994531e-1f);
    p = fmaf(p, f, 1.0f);
    return __uint_as_float(__float_as_uint(p) + ((unsigned)n << 23));
}

// ---------------- block reductions (8 warps) ----------------
__device__ __forceinline__ float blockMaxF(float v, float* red, int tid) {
    int lane = tid & 31, w = tid >> 5;
    #pragma unroll
    for (int k = 16; k; k >>= 1) v = fmaxf(v, __shfl_xor_sync(~0u, v, k));
    if (lane == 0) red[w] = v;
    __syncthreads();
    if (tid < 32) {
        float m = (tid < 8) ? red[tid] : -INFINITY;
        #pragma unroll
        for (int k = 4; k; k >>= 1) m = fmaxf(m, __shfl_xor_sync(~0u, m, k));
        if (tid == 0) red[0] = m;
    }
    __syncthreads();
    float r = red[0]; __syncthreads();
    return r;
}
__device__ __forceinline__ int blockSumI(int v, int* redi, int tid) {
    int lane = tid & 31, w = tid >> 5;
    #pragma unroll
    for (int k = 16; k; k >>= 1) v += __shfl_xor_sync(~0u, v, k);
    if (lane == 0) redi[w] = v;
    __syncthreads();
    if (tid < 32) {
        int s = (tid < 8) ? redi[tid] : 0;
        #pragma unroll
        for (int k = 4; k; k >>= 1) s += __shfl_xor_sync(~0u, s, k);
        if (tid == 0) redi[0] = s;
    }
    __syncthreads();
    int r = redi[0]; __syncthreads();
    return r;
}

// full-row count of (> t) from global (fallback only)
__device__ __forceinline__ int cgtGlobal(const float* __restrict__ x, float t,
                                         int tid, int* redi) {
    int c = 0;
    #pragma unroll 8
    for (int i = tid; i < VV; i += NT1) c += (__ldg(x + i) > t);
    return blockSumI(c, redi, tid);
}

extern __shared__ float smk1[];

__global__ void __launch_bounds__(NT1, 6)
k1_topk(const float* __restrict__ inp,
        const float* __restrict__ W1, const float* __restrict__ b1,
        const float* __restrict__ W2, const float* __restrict__ b2,
        const float* __restrict__ W3, const float* __restrict__ b3)
{
    float* samp = smk1;           // [4096] first 4096 row elements
    float* buf  = smk1 + 4096;    // [FCAP] finalists
    __shared__ float redf[8];
    __shared__ int   redi[8];
    __shared__ int   sCnt;
    __shared__ float sh1[5];

    const int tid  = threadIdx.x;
    const int lane = tid & 31;
    const int wid  = tid >> 5;
    const int row  = blockIdx.x;
    const float* x = inp + (size_t)row * VV;

    if (tid == 0) sCnt = 0;

    // ---- Phase A: first 4096 elems -> smem sample (also warms L2) ----
    float sx = -INFINITY;
    #pragma unroll
    for (int j = 0; j < 16; j++) {
        float s = __ldg(x + j * NT1 + tid);
        samp[j * NT1 + tid] = s;
        sx = fmaxf(sx, s);
    }
    float sampmax = blockMaxF(sx, redf, tid);   // barriers also publish sCnt=0

    // ---- Phase B: bisect threshold on the sample, target count in [CS_LO, CS_HI] ----
    float t;
    {
        auto countSamp = [&](float v) {
            int c = 0;
            #pragma unroll
            for (int j = 0; j < 16; j++) c += (samp[j * NT1 + tid] > v);
            return blockSumI(c, redi, tid);
        };
        float gap = 4.0f, lo = sampmax - gap, hi = sampmax;
        int clo = countSamp(lo);
        for (int e = 0; e < 16 && clo < CS_LO; e++) {
            gap *= 4.0f; lo = sampmax - gap;
            clo = countSamp(lo);
        }
        t = lo;
        if (clo > CS_HI) {
            int found = 0;
            for (int it = 0; it < 24 && !found; it++) {
                float mid = 0.5f * (lo + hi);
                if (mid <= lo || mid >= hi) { t = hi; break; }   // tie plateau
                int c = countSamp(mid);
                if (c >= CS_LO && c <= CS_HI) { t = mid; found = 1; }
                else if (c > CS_HI) lo = mid; else hi = mid;
            }
            if (!found && t == lo) t = hi;
        }
    }

    // ---- Phase C: single float4 stream: exact max + direct gather into buf ----
    float mx = -INFINITY;
    {
        const int head = (4 - (int)(((size_t)row * VV) & 3)) & 3;  // x is inp+row*VV; inp 256B-aligned
        if (tid < head) {
            float v = __ldg(x + tid);
            mx = fmaxf(mx, v);
            if (v > t) { int p = atomicAdd(&sCnt, 1); if (p < FCAP) buf[p] = v; }
        }
        const float4* x4 = (const float4*)(x + head);
        const int n4 = (VV - head) >> 2;
        const int kfull = n4 >> 10;                     // batches of 4 quads x 256 thr
        #pragma unroll 1
        for (int k = 0; k < kfull; k++) {
            int base = (k << 10) + tid;
            float4 q0 = __ldg(x4 + base);
            float4 q1 = __ldg(x4 + base + 256);
            float4 q2 = __ldg(x4 + base + 512);
            float4 q3 = __ldg(x4 + base + 768);
            #define PROC(q) do { \
                mx = fmaxf(mx, fmaxf(fmaxf(q.x, q.y), fmaxf(q.z, q.w))); \
                if (q.x > t) { int p = atomicAdd(&sCnt, 1); if (p < FCAP) buf[p] = q.x; } \
                if (q.y > t) { int p = atomicAdd(&sCnt, 1); if (p < FCAP) buf[p] = q.y; } \
                if (q.z > t) { int p = atomicAdd(&sCnt, 1); if (p < FCAP) buf[p] = q.z; } \
                if (q.w > t) { int p = atomicAdd(&sCnt, 1); if (p < FCAP) buf[p] = q.w; } \
            } while (0)
            PROC(q0); PROC(q1); PROC(q2); PROC(q3);
        }
        #pragma unroll 1
        for (int i = (kfull << 10) + tid; i < n4; i += NT1) {
            float4 q = __ldg(x4 + i);
            PROC(q);
            #undef PROC
        }
        for (int i = head + (n4 << 2) + tid; i < VV; i += NT1) {
            float v = __ldg(x + i);
            mx = fmaxf(mx, v);
            if (v > t) { int p = atomicAdd(&sCnt, 1); if (p < FCAP) buf[p] = v; }
        }
    }
    float M = blockMaxF(mx, redf, tid);
    int   C = sCnt;                                   // valid: blockMaxF synced
    float tSel = t;

    // ---- Phase D: certificate check; rare exact fallback ----
    if (C < TOPK || C > FCAP) {
        float gap = 8.0f, lo = M - gap, hi = M;
        int c = cgtGlobal(x, lo, tid, redi);
        for (int e = 0; e < 12 && c < TOPK; e++) {
            gap *= 4.0f; lo = M - gap;
            c = cgtGlobal(x, lo, tid, redi);
        }
        float ts = hi; int found = 0;
        if (c >= TOPK && c <= FCAP) { ts = lo; found = 1; }
        for (int it = 0; it < 50 && !found; it++) {
            float mid = 0.5f * (lo + hi);
            if (mid <= lo || mid >= hi) break;        // tie plateau -> hi
            c = cgtGlobal(x, mid, tid, redi);
            if (c >= TOPK && c <= FCAP) { ts = mid; found = 1; }
            else if (c > FCAP) lo = mid; else hi = mid;
        }
        tSel = ts;
        __syncthreads();
        if (tid == 0) sCnt = 0;
        __syncthreads();
        #pragma unroll 4
        for (int i = tid; i < VV; i += NT1) {
            float v = __ldg(x + i);
            if (v > tSel) { int p = atomicAdd(&sCnt, 1); if (p < FCAP) buf[p] = v; }
        }
        __syncthreads();
        C = sCnt;
    }
    int bc = min(C, FCAP);

    // ---- Phase E: pad + bitonic sort 512 descending (2 elems/thread) ----
    if (tid      >= bc) buf[tid]       = -INFINITY;
    if (tid + 256 >= bc) buf[tid + 256] = -INFINITY;
    __syncthreads();
    #pragma unroll 1
    for (int k = 2; k <= FCAP; k <<= 1) {
        #pragma unroll 1
        for (int j = k >> 1; j > 0; j >>= 1) {
            #pragma unroll
            for (int mbase = 0; mbase < FCAP; mbase += NT1) {
                int i = mbase + tid, ixj = i ^ j;
                if (ixj > i) {
                    float va = buf[i], vb = buf[ixj];
                    bool desc = ((i & k) == 0);
                    if (desc ? (va < vb) : (va > vb)) { buf[i] = vb; buf[ixj] = va; }
                }
            }
            __syncthreads();
        }
    }
    // tie-plateau fill: any missing top-k entries equal tSel by construction
    if (tid < TOPK && tid >= bc) buf[tid] = tSel;
    __syncthreads();

    // ---- Phase F: tiny MLP -> temperature -> (a, b) ----
    if (wid < 5) {
        float acc = 0.0f;
        #pragma unroll
        for (int i = lane; i < TOPK; i += 32)
            acc = fmaf(__ldg(W1 + wid * TOPK + i), buf[i], acc);
        #pragma unroll
        for (int k = 16; k; k >>= 1) acc += __shfl_xor_sync(~0u, acc, k);
        if (lane == 0) sh1[wid] = fmaxf(acc + __ldg(b1 + wid), 0.0f);
    }
    __syncthreads();
    if (tid == 0) {
        float h2[5];
        #pragma unroll
        for (int j = 0; j < 5; ++j) {
            float a2 = __ldg(b2 + j);
            #pragma unroll
            for (int i = 0; i < 5; ++i) a2 = fmaf(__ldg(W2 + j * 5 + i), sh1[i], a2);
            h2[j] = fmaxf(a2, 0.0f);
        }
        float t0 = __ldg(b3);
        #pragma unroll
        for (int i = 0; i < 5; ++i) t0 = fmaf(__ldg(W3 + i), h2[i], t0);
        t0 = fabsf(t0);
        float sp   = (t0 > 20.0f) ? t0 : log1pf(expf(t0));
        float temp = fmaxf(sp, 1e-5f);
        float a    = 1.44269504088896340736f / temp;
        g_a[row] = a;
        g_b[row] = -M * a;
    }
}

__global__ void __launch_bounds__(NT2)
k2_sumexp(const float* __restrict__ inp)
{
    const int row = blockIdx.x >> 2;
    const int seg = blockIdx.x & 3;
    const int tid = threadIdx.x;
    const float* x = inp + (size_t)row * VV;
    const float a = __ldg(&g_a[row]);
    const float b = __ldg(&g_b[row]);
    const int start = seg * SEGLEN;
    const int end   = min(VV, start + SEGLEN);

    float s = 0.0f;
    int i = start + tid;
    for (; i + 7 * NT2 < end; i += 8 * NT2) {
        float v[8];
        #pragma unroll
        for (int j = 0; j < 8; j++) v[j] = __ldg(x + i + j * NT2);
        #pragma unroll
        for (int j = 0; j < 8; j++) s += exp2_fast(fmaf(v[j], a, b));
    }
    for (; i < end; i += NT2) s += exp2_fast(fmaf(__ldg(x + i), a, b));

    __shared__ float red[8];
    int lane = tid & 31, w = tid >> 5;
    #pragma unroll
    for (int k = 16; k; k >>= 1) s += __shfl_xor_sync(~0u, s, k);
    if (lane == 0) red[w] = s;
    __syncthreads();
    if (tid == 0) {
        float tot = 0.0f;
        #pragma unroll
        for (int k = 0; k < NT2 / 32; k++) tot += red[k];
        g_part[row * SEG + seg] = tot;
    }
}

__global__ void k3_final(const float* __restrict__ inp,
                         const int* __restrict__ tokens,
                         float* __restrict__ out, int nrows)
{
    int r = blockIdx.x * blockDim.x + threadIdx.x;
    if (r >= nrows) return;
    float s = g_part[r * SEG + 0] + g_part[r * SEG + 1]
            + g_part[r * SEG + 2] + g_part[r * SEG + 3];
    int tok = tokens[r];
    tok = (tok < 0) ? 0 : ((tok >= VV) ? VV - 1 : tok);
    float xt = __ldg(inp + (size_t)r * VV + tok);
    out[r] = exp2_fast(fmaf(xt, g_a[r], g_b[r])) / s;
}

extern "C" void kernel_launch(void* const* d_in, const int* in_sizes, int n_in,
                              void* d_out, int out_size)
{
    const float* inp    = (const float*)d_in[0];
    const int*   tokens = (const int*)d_in[1];
    const float* W1     = (const float*)d_in[2];
    const float* b1     = (const float*)d_in[3];
    const float* W2     = (const float*)d_in[4];
    const float* b2     = (const float*)d_in[5];
    const float* W3     = (const float*)d_in[6];
    const float* b3     = (const float*)d_in[7];
    float*       o      = (float*)d_out;

    int N = in_sizes[1];
    if (N > MAXN) N = MAXN;

    size_t sm1 = (size_t)(4096 + FCAP) * sizeof(float);   // 18 KB
    cudaFuncSetAttribute(k1_topk, cudaFuncAttributeMaxDynamicSharedMemorySize, (int)sm1);

    k1_topk<<<N, NT1, sm1>>>(inp, W1, b1, W2, b2, W3, b3);
    k2_sumexp<<<N * SEG, NT2>>>(inp);
    k3_final<<<(N + 255) / 256, 256>>>(inp, tokens, o, N);
}

// round 6
// speedup vs baseline: 2.6696x; 1.0200x over previous
#include <cuda_runtime.h>
#include <math.h>

#define VV      50257
#define NT1     256
#define FCAP    512                  // finalist buffer
#define TOPK    100
#define CS_LO   16                   // sample-count target window
#define CS_HI   32
#define SEG     4
#define SEGLEN  12565
#define MAXN    8192
#define NT2     256

__device__ float g_a[MAXN];
__device__ float g_b[MAXN];
__device__ float g_part[MAXN * SEG];

// 2^y via round-to-int bit trick + degree-5 poly; FMA/ALU only, no MUFU.
__device__ __forceinline__ float exp2_fast(float y) {
    y = fmaxf(y, -120.0f);
    float r = y + 12582912.0f;
    int   n = __float_as_int(r) - 0x4B400000;
    float f = y - (r - 12582912.0f);
    float p = 1.3333558146428443e-3f;
    p = fmaf(p, f, 9.6181291076284772e-3f);
    p = fmaf(p, f, 5.5504108664821580e-2f);
    p = fmaf(p, f, 2.4022650695910071e-1f);
    p = fmaf(p, f, 6.9314718055994531e-1f);
    p = fmaf(p, f, 1.0f);
    return __uint_as_float(__float_as_uint(p) + ((unsigned)n << 23));
}

// ---------------- block reductions (8 warps) ----------------
__device__ __forceinline__ float blockMaxF(float v, float* red, int tid) {
    int lane = tid & 31, w = tid >> 5;
    #pragma unroll
    for (int k = 16; k; k >>= 1) v = fmaxf(v, __shfl_xor_sync(~0u, v, k));
    if (lane == 0) red[w] = v;
    __syncthreads();
    if (tid < 32) {
        float m = (tid < 8) ? red[tid] : -INFINITY;
        #pragma unroll
        for (int k = 4; k; k >>= 1) m = fmaxf(m, __shfl_xor_sync(~0u, m, k));
        if (tid == 0) red[0] = m;
    }
    __syncthreads();
    float r = red[0]; __syncthreads();
    return r;
}
__device__ __forceinline__ int blockSumI(int v, int* redi, int tid) {
    int lane = tid & 31, w = tid >> 5;
    #pragma unroll
    for (int k = 16; k; k >>= 1) v += __shfl_xor_sync(~0u, v, k);
    if (lane == 0) redi[w] = v;
    __syncthreads();
    if (tid < 32) {
        int s = (tid < 8) ? redi[tid] : 0;
        #pragma unroll
        for (int k = 4; k; k >>= 1) s += __shfl_xor_sync(~0u, s, k);
        if (tid == 0) redi[0] = s;
    }
    __syncthreads();
    int r = redi[0]; __syncthreads();
    return r;
}

// full-row count of (> t) from global (fallback only)
__device__ __forceinline__ int cgtGlobal(const float* __restrict__ x, float t,
                                         int tid, int* redi) {
    int c = 0;
    #pragma unroll 8
    for (int i = tid; i < VV; i += NT1) c += (__ldg(x + i) > t);
    return blockSumI(c, redi, tid);
}

extern __shared__ float smk1[];

__global__ void __launch_bounds__(NT1, 6)
k1_topk(const float* __restrict__ inp,
        const float* __restrict__ W1, const float* __restrict__ b1,
        const float* __restrict__ W2, const float* __restrict__ b2,
        const float* __restrict__ W3, const float* __restrict__ b3)
{
    float* samp = smk1;           // [4096] first 4096 row elements
    float* buf  = smk1 + 4096;    // [FCAP] finalists
    __shared__ float redf[8];
    __shared__ int   redi[8];
    __shared__ int   sCnt;
    __shared__ float sh1[5];

    const int tid  = threadIdx.x;
    const int lane = tid & 31;
    const int wid  = tid >> 5;
    const int row  = blockIdx.x;
    const float* x = inp + (size_t)row * VV;

    if (tid == 0) sCnt = 0;

    // ---- Phase A: first 4096 elems -> smem sample (also warms L2) ----
    float sx = -INFINITY;
    #pragma unroll
    for (int j = 0; j < 16; j++) {
        float s = __ldg(x + j * NT1 + tid);
        samp[j * NT1 + tid] = s;
        sx = fmaxf(sx, s);
    }
    float sampmax = blockMaxF(sx, redf, tid);   // barriers also publish sCnt=0

    // ---- Phase B: bisect threshold on the sample, target count in [CS_LO, CS_HI] ----
    float t;
    {
        auto countSamp = [&](float v) {
            int c = 0;
            #pragma unroll
            for (int j = 0; j < 16; j++) c += (samp[j * NT1 + tid] > v);
            return blockSumI(c, redi, tid);
        };
        float gap = 4.0f, lo = sampmax - gap, hi = sampmax;
        int clo = countSamp(lo);
        for (int e = 0; e < 16 && clo < CS_LO; e++) {
            gap *= 4.0f; lo = sampmax - gap;
            clo = countSamp(lo);
        }
        t = lo;
        if (clo > CS_HI) {
            int found = 0;
            for (int it = 0; it < 24 && !found; it++) {
                float mid = 0.5f * (lo + hi);
                if (mid <= lo || mid >= hi) { t = hi; break; }   // tie plateau
                int c = countSamp(mid);
                if (c >= CS_LO && c <= CS_HI) { t = mid; found = 1; }
                else if (c > CS_HI) lo = mid; else hi = mid;
            }
            if (!found && t == lo) t = hi;
        }
    }

    // ---- Phase C: single float4 stream: exact max + direct gather into buf.
    //      Winner test hoisted to 16-elem batch granularity: ONE branch per
    //      batch (P(taken) ~ 9%) instead of 16 predicated-atomic regions. ----
    float mx = -INFINITY;
    {
        const int head = (4 - (int)(((size_t)row * VV) & 3)) & 3;
        if (tid < head) {
            float v = __ldg(x + tid);
            mx = fmaxf(mx, v);
            if (v > t) { int p = atomicAdd(&sCnt, 1); if (p < FCAP) buf[p] = v; }
        }
        const float4* x4 = (const float4*)(x + head);
        const int n4 = (VV - head) >> 2;
        const int kfull = n4 >> 10;                     // batches of 4 quads x 256 thr

        #define CHECKQ(q) do { \
            if (q.x > t) { int p = atomicAdd(&sCnt, 1); if (p < FCAP) buf[p] = q.x; } \
            if (q.y > t) { int p = atomicAdd(&sCnt, 1); if (p < FCAP) buf[p] = q.y; } \
            if (q.z > t) { int p = atomicAdd(&sCnt, 1); if (p < FCAP) buf[p] = q.z; } \
            if (q.w > t) { int p = atomicAdd(&sCnt, 1); if (p < FCAP) buf[p] = q.w; } \
        } while (0)

        #pragma unroll 1
        for (int k = 0; k < kfull; k++) {
            int base = (k << 10) + tid;
            float4 q0 = __ldg(x4 + base);
            float4 q1 = __ldg(x4 + base + 256);
            float4 q2 = __ldg(x4 + base + 512);
            float4 q3 = __ldg(x4 + base + 768);
            float m0 = fmaxf(fmaxf(q0.x, q0.y), fmaxf(q0.z, q0.w));
            float m1 = fmaxf(fmaxf(q1.x, q1.y), fmaxf(q1.z, q1.w));
            float m2 = fmaxf(fmaxf(q2.x, q2.y), fmaxf(q2.z, q2.w));
            float m3 = fmaxf(fmaxf(q3.x, q3.y), fmaxf(q3.z, q3.w));
            float bmx = fmaxf(fmaxf(m0, m1), fmaxf(m2, m3));
            mx = fmaxf(mx, bmx);
            if (bmx > t) {                              // rare (~9% of thread-batches)
                CHECKQ(q0); CHECKQ(q1); CHECKQ(q2); CHECKQ(q3);
            }
        }
        #pragma unroll 1
        for (int i = (kfull << 10) + tid; i < n4; i += NT1) {
            float4 q = __ldg(x4 + i);
            float m0 = fmaxf(fmaxf(q.x, q.y), fmaxf(q.z, q.w));
            mx = fmaxf(mx, m0);
            if (m0 > t) CHECKQ(q);
        }
        #undef CHECKQ
        for (int i = head + (n4 << 2) + tid; i < VV; i += NT1) {
            float v = __ldg(x + i);
            mx = fmaxf(mx, v);
            if (v > t) { int p = atomicAdd(&sCnt, 1); if (p < FCAP) buf[p] = v; }
        }
    }
    float M = blockMaxF(mx, redf, tid);
    int   C = sCnt;                                   // valid: blockMaxF synced
    float tSel = t;

    // ---- Phase D: certificate check; rare exact fallback ----
    if (C < TOPK || C > FCAP) {
        float gap = 8.0f, lo = M - gap, hi = M;
        int c = cgtGlobal(x, lo, tid, redi);
        for (int e = 0; e < 12 && c < TOPK; e++) {
            gap *= 4.0f; lo = M - gap;
            c = cgtGlobal(x, lo, tid, redi);
        }
        float ts = hi; int found = 0;
        if (c >= TOPK && c <= FCAP) { ts = lo; found = 1; }
        for (int it = 0; it < 50 && !found; it++) {
            float mid = 0.5f * (lo + hi);
            if (mid <= lo || mid >= hi) break;        // tie plateau -> hi
            c = cgtGlobal(x, mid, tid, redi);
            if (c >= TOPK && c <= FCAP) { ts = mid; found = 1; }
            else if (c > FCAP) lo = mid; else hi = mid;
        }
        tSel = ts;
        __syncthreads();
        if (tid == 0) sCnt = 0;
        __syncthreads();
        #pragma unroll 4
        for (int i = tid; i < VV; i += NT1) {
            float v = __ldg(x + i);
            if (v > tSel) { int p = atomicAdd(&sCnt, 1); if (p < FCAP) buf[p] = v; }
        }
        __syncthreads();
        C = sCnt;
    }
    int bc = min(C, FCAP);

    // ---- Phase E: pad + bitonic sort 512 descending (2 elems/thread) ----
    if (tid       >= bc) buf[tid]       = -INFINITY;
    if (tid + 256 >= bc) buf[tid + 256] = -INFINITY;
    __syncthreads();
    #pragma unroll 1
    for (int k = 2; k <= FCAP; k <<= 1) {
        #pragma unroll 1
        for (int j = k >> 1; j > 0; j >>= 1) {
            #pragma unroll
            for (int mbase = 0; mbase < FCAP; mbase += NT1) {
                int i = mbase + tid, ixj = i ^ j;
                if (ixj > i) {
                    float va = buf[i], vb = buf[ixj];
                    bool desc = ((i & k) == 0);
                    if (desc ? (va < vb) : (va > vb)) { buf[i] = vb; buf[ixj] = va; }
                }
            }
            __syncthreads();
        }
    }
    // tie-plateau fill: any missing top-k entries equal tSel by construction
    if (tid < TOPK && tid >= bc) buf[tid] = tSel;
    __syncthreads();

    // ---- Phase F: tiny MLP -> temperature -> (a, b) ----
    if (wid < 5) {
        float acc = 0.0f;
        #pragma unroll
        for (int i = lane; i < TOPK; i += 32)
            acc = fmaf(__ldg(W1 + wid * TOPK + i), buf[i], acc);
        #pragma unroll
        for (int k = 16; k; k >>= 1) acc += __shfl_xor_sync(~0u, acc, k);
        if (lane == 0) sh1[wid] = fmaxf(acc + __ldg(b1 + wid), 0.0f);
    }
    __syncthreads();
    if (tid == 0) {
        float h2[5];
        #pragma unroll
        for (int j = 0; j < 5; ++j) {
            float a2 = __ldg(b2 + j);
            #pragma unroll
            for (int i = 0; i < 5; ++i) a2 = fmaf(__ldg(W2 + j * 5 + i), sh1[i], a2);
            h2[j] = fmaxf(a2, 0.0f);
        }
        float t0 = __ldg(b3);
        #pragma unroll
        for (int i = 0; i < 5; ++i) t0 = fmaf(__ldg(W3 + i), h2[i], t0);
        t0 = fabsf(t0);
        float sp   = (t0 > 20.0f) ? t0 : log1pf(expf(t0));
        float temp = fmaxf(sp, 1e-5f);
        float a    = 1.44269504088896340736f / temp;
        g_a[row] = a;
        g_b[row] = -M * a;
    }
}

__global__ void __launch_bounds__(NT2)
k2_sumexp(const float* __restrict__ inp)
{
    const int row = blockIdx.x >> 2;
    const int seg = blockIdx.x & 3;
    const int tid = threadIdx.x;
    const float* x = inp + (size_t)row * VV;
    const float a = __ldg(&g_a[row]);
    const float b = __ldg(&g_b[row]);
    const int start = seg * SEGLEN;
    const int end   = min(VV, start + SEGLEN);

    float s = 0.0f;
    int i = start + tid;
    for (; i + 7 * NT2 < end; i += 8 * NT2) {
        float v[8];
        #pragma unroll
        for (int j = 0; j < 8; j++) v[j] = __ldg(x + i + j * NT2);
        #pragma unroll
        for (int j = 0; j < 8; j++) s += exp2_fast(fmaf(v[j], a, b));
    }
    for (; i < end; i += NT2) s += exp2_fast(fmaf(__ldg(x + i), a, b));

    __shared__ float red[8];
    int lane = tid & 31, w = tid >> 5;
    #pragma unroll
    for (int k = 16; k; k >>= 1) s += __shfl_xor_sync(~0u, s, k);
    if (lane == 0) red[w] = s;
    __syncthreads();
    if (tid == 0) {
        float tot = 0.0f;
        #pragma unroll
        for (int k = 0; k < NT2 / 32; k++) tot += red[k];
        g_part[row * SEG + seg] = tot;
    }
}

__global__ void k3_final(const float* __restrict__ inp,
                         const int* __restrict__ tokens,
                         float* __restrict__ out, int nrows)
{
    int r = blockIdx.x * blockDim.x + threadIdx.x;
    if (r >= nrows) return;
    float s = g_part[r * SEG + 0] + g_part[r * SEG + 1]
            + g_part[r * SEG + 2] + g_part[r * SEG + 3];
    int tok = tokens[r];
    tok = (tok < 0) ? 0 : ((tok >= VV) ? VV - 1 : tok);
    float xt = __ldg(inp + (size_t)r * VV + tok);
    out[r] = exp2_fast(fmaf(xt, g_a[r], g_b[r])) / s;
}

extern "C" void kernel_launch(void* const* d_in, const int* in_sizes, int n_in,
                              void* d_out, int out_size)
{
    const float* inp    = (const float*)d_in[0];
    const int*   tokens = (const int*)d_in[1];
    const float* W1     = (const float*)d_in[2];
    const float* b1     = (const float*)d_in[3];
    const float* W2     = (const float*)d_in[4];
    const float* b2     = (const float*)d_in[5];
    const float* W3     = (const float*)d_in[6];
    const float* b3     = (const float*)d_in[7];
    float*       o      = (float*)d_out;

    int N = in_sizes[1];
    if (N > MAXN) N = MAXN;

    size_t sm1 = (size_t)(4096 + FCAP) * sizeof(float);   // 18 KB
    cudaFuncSetAttribute(k1_topk, cudaFuncAttributeMaxDynamicSharedMemorySize, (int)sm1);

    k1_topk<<<N, NT1, sm1>>>(inp, W1, b1, W2, b2, W3, b3);
    k2_sumexp<<<N * SEG, NT2>>>(inp);
    k3_final<<<(N + 255) / 256, 256>>>(inp, tokens, o, N);
}